// round 10
// baseline (speedup 1.0000x reference)
#include <cuda_runtime.h>
#include <stdint.h>

// Problem constants (fixed by the reference)
#define BB 32
#define TT 256
#define DD 384
#define ML 2048
#define D4 (DD / 4)      // 96 float4 per row
#define RPT 8            // rows per thread
#define NY 4             // y-slices per block
#define RPB (RPT*NY)     // 32 rows per block
#define TILE_BYTES (RPB * DD * 4)              // 49152 = 48KB output tile
#define SMEM_TOTAL (TILE_BYTES + (TT + 8 + RPB) * 4)

// Single fused kernel, TMA-store version. Block = (96,4) = 384 threads; each
// block: shfl-scan the batch's 256 int32 durations, scatter its 32-row idx
// window, gather x rows into a 48KB smem tile, then ONE cp.async.bulk store
// smem->global (bypasses L1 / per-STG issue cost entirely).
__global__ void lr_fused_kernel(const float4* __restrict__ x,
                                const int* __restrict__ dur,
                                float4* __restrict__ out,
                                float* __restrict__ mel_out) {
    extern __shared__ char smem[];
    float4* tile = (float4*)smem;                       // RPB*96 float4
    int*    cs   = (int*)(smem + TILE_BYTES);           // 256 inclusive csum
    int*    wsum = cs + TT;                             // 8 warp totals
    int*    sidx = wsum + 8;                            // RPB row->token idx

    const int tid  = threadIdx.y * blockDim.x + threadIdx.x;  // 0..383
    const int r0   = blockIdx.x * RPB;       // first output row of this block
    const int b    = r0 >> 11;               // batch = r0 / ML
    const int rloc = r0 & (ML - 1);          // row offset within batch

    // init idx window
    if (tid >= TT && tid < TT + RPB) sidx[tid - TT] = -1;

    int myd = 0;
    if (tid < TT) {
        const int lane = tid & 31;
        const int w    = tid >> 5;           // warp 0..7
        myd = dur[b * TT + tid];

        // warp-level inclusive scan (5 shfl steps)
        int s = myd;
        #pragma unroll
        for (int off = 1; off < 32; off <<= 1) {
            int up = __shfl_up_sync(0xFFFFFFFFu, s, off);
            if (lane >= off) s += up;
        }
        cs[tid] = s;
        if (lane == 31) wsum[w] = s;
    }
    __syncthreads();

    if (tid < TT) {
        const int w = tid >> 5;
        int off = 0;
        #pragma unroll
        for (int i = 0; i < TT / 32 - 1; i++)
            if (i < w) off += wsum[i];
        const int incl = cs[tid] + off;      // inclusive prefix
        cs[tid] = incl;

        // mel_len (float32 tail — proven R4->R5); one block per batch writes
        if (tid == TT - 1 && rloc == 0 && mel_out != nullptr)
            mel_out[b] = (float)incl;
    }
    __syncthreads();

    // Scatter this block's 32-row window: token tid covers [start, end)
    if (tid < TT) {
        const int end   = cs[tid];
        const int start = end - myd;         // exclusive prefix
        int lo = start > rloc ? start : rloc;
        int hi = end < rloc + RPB ? end : rloc + RPB;
        for (int f = lo; f < hi; f++) sidx[f - rloc] = tid;
    }
    __syncthreads();

    // ---- gather into smem tile: 8 rows per thread, MLP=8 ----
    const int j  = threadIdx.x;              // 0..95
    const int ry = threadIdx.y * RPT;        // this thread's first local row

    int idx[RPT];
    #pragma unroll
    for (int i = 0; i < RPT; i++) idx[i] = sidx[ry + i];

    float4 v[RPT];
    #pragma unroll
    for (int i = 0; i < RPT; i++) {
        v[i] = make_float4(0.f, 0.f, 0.f, 0.f);
        if (idx[i] >= 0) v[i] = __ldg(&x[(b * TT + idx[i]) * D4 + j]);
    }
    #pragma unroll
    for (int i = 0; i < RPT; i++) tile[(ry + i) * D4 + j] = v[i];

    __syncthreads();

    // ---- one bulk TMA store: 48KB smem -> global (contiguous rows) ----
    if (tid == 0) {
        asm volatile("fence.proxy.async.shared::cta;" ::: "memory");
        uint32_t saddr;
        asm("{ .reg .u64 t; cvta.to.shared.u64 t, %1; cvt.u32.u64 %0, t; }"
            : "=r"(saddr) : "l"(tile));
        const float4* gdst = out + (long long)r0 * D4;
        asm volatile("cp.async.bulk.global.shared::cta.bulk_group [%0], [%1], %2;"
                     :: "l"(gdst), "r"(saddr), "n"(TILE_BYTES) : "memory");
        asm volatile("cp.async.bulk.commit_group;" ::: "memory");
        asm volatile("cp.async.bulk.wait_group.read 0;" ::: "memory");
    }
}

extern "C" void kernel_launch(void* const* d_in, const int* in_sizes, int n_in,
                              void* d_out, int out_size) {
    const float* x   = (const float*)d_in[0];
    const int*   dur = (const int*)d_in[1];   // harness stores duration as int32
    // d_in[2] = max_len (scalar, constant 2048)

    float* out = (float*)d_out;
    const long long main_elems = (long long)BB * ML * DD;
    const long long extra = (long long)out_size - main_elems;
    float* mel_out = (extra > 0) ? (out + main_elems) : nullptr;

    static bool attr_set = false;
    if (!attr_set) {
        cudaFuncSetAttribute(lr_fused_kernel,
                             cudaFuncAttributeMaxDynamicSharedMemorySize,
                             SMEM_TOTAL);
        attr_set = true;
    }

    dim3 blk(D4, NY);                    // 384 threads
    dim3 grd((BB * ML) / RPB);           // 2048 blocks
    lr_fused_kernel<<<grd, blk, SMEM_TOTAL>>>((const float4*)x, dur,
                                              (float4*)out, mel_out);
}

// round 11
// speedup vs baseline: 1.1009x; 1.1009x over previous
#include <cuda_runtime.h>
#include <stdint.h>

// Problem constants (fixed by the reference)
#define BB 32
#define TT 256
#define DD 384
#define ML 2048
#define D4 (DD / 4)   // 96 float4 per row
#define RPT 8         // rows per thread
#define NY 4          // y-slices per block
#define RPB (RPT*NY)  // 32 rows per block

// Streaming (evict-first) 128-bit store: output is write-once; keeping it
// out of L2 preserves x/idx residency across graph replays (proven R9 vs R10).
__device__ __forceinline__ void stg_cs_128(float4* p, float4 v) {
    asm volatile("st.global.cs.v4.f32 [%0], {%1, %2, %3, %4};"
                 :: "l"(p), "f"(v.x), "f"(v.y), "f"(v.z), "f"(v.w)
                 : "memory");
}

// Single fused kernel. Block = (96,4) = 384 threads; 32 consecutive output
// rows of one batch per block. Prelude: shfl scan (3 barriers) + scatter of
// the block's 32-row idx window. Gather exploits run-length duplication:
// idx[i]==idx[i-1] (warp-uniform) -> reuse register instead of reloading.
__global__ void lr_fused_kernel(const float4* __restrict__ x,
                                const int* __restrict__ dur,
                                float4* __restrict__ out,
                                float* __restrict__ mel_out) {
    __shared__ int cs[TT];         // inclusive cumsum of durations
    __shared__ int wsum[TT / 32];  // per-warp totals (8)
    __shared__ int sidx[RPB];      // source-token idx for block rows (-1 = pad)

    const int tid  = threadIdx.y * blockDim.x + threadIdx.x;  // 0..383
    const int r0   = blockIdx.x * RPB;       // first output row of this block
    const int b    = r0 >> 11;               // batch = r0 / ML
    const int rloc = r0 & (ML - 1);          // row offset within batch

    // init idx window
    if (tid >= TT && tid < TT + RPB) sidx[tid - TT] = -1;

    int myd = 0;
    if (tid < TT) {
        const int lane = tid & 31;
        const int w    = tid >> 5;           // warp 0..7
        myd = dur[b * TT + tid];

        // warp-level inclusive scan (5 shfl steps)
        int s = myd;
        #pragma unroll
        for (int off = 1; off < 32; off <<= 1) {
            int up = __shfl_up_sync(0xFFFFFFFFu, s, off);
            if (lane >= off) s += up;
        }
        cs[tid] = s;
        if (lane == 31) wsum[w] = s;
    }
    __syncthreads();

    if (tid < TT) {
        const int w = tid >> 5;
        int off = 0;
        #pragma unroll
        for (int i = 0; i < TT / 32 - 1; i++)
            if (i < w) off += wsum[i];
        const int incl = cs[tid] + off;      // inclusive prefix
        cs[tid] = incl;

        // mel_len (float32 tail — proven R4->R5); one block per batch writes
        if (tid == TT - 1 && rloc == 0 && mel_out != nullptr)
            mel_out[b] = (float)incl;
    }
    __syncthreads();

    // Scatter this block's 32-row window: token tid covers [start, end)
    if (tid < TT) {
        const int end   = cs[tid];
        const int start = end - myd;         // exclusive prefix
        int lo = start > rloc ? start : rloc;
        int hi = end < rloc + RPB ? end : rloc + RPB;
        for (int f = lo; f < hi; f++) sidx[f - rloc] = tid;
    }
    __syncthreads();

    // ---- gather: 8 rows per thread; duplicate-row register reuse ----
    const int j  = threadIdx.x;              // 0..95
    const int ry = threadIdx.y * RPT;        // this thread's first local row

    int idx[RPT];
    #pragma unroll
    for (int i = 0; i < RPT; i++) idx[i] = sidx[ry + i];

    float4 v[RPT];
    #pragma unroll
    for (int i = 0; i < RPT; i++) {
        if (i > 0 && idx[i] == idx[i - 1]) {
            v[i] = v[i - 1];                 // warp-uniform duplicate: reuse
        } else if (idx[i] >= 0) {
            v[i] = __ldg(&x[(b * TT + idx[i]) * D4 + j]);
        } else {
            v[i] = make_float4(0.f, 0.f, 0.f, 0.f);
        }
    }

    float4* basep = (float4*)out + (long long)(r0 + ry) * D4 + j;
    #pragma unroll
    for (int i = 0; i < RPT; i++) stg_cs_128(basep + (long long)i * D4, v[i]);
}

extern "C" void kernel_launch(void* const* d_in, const int* in_sizes, int n_in,
                              void* d_out, int out_size) {
    const float* x   = (const float*)d_in[0];
    const int*   dur = (const int*)d_in[1];   // harness stores duration as int32
    // d_in[2] = max_len (scalar, constant 2048)

    float* out = (float*)d_out;
    const long long main_elems = (long long)BB * ML * DD;
    const long long extra = (long long)out_size - main_elems;
    float* mel_out = (extra > 0) ? (out + main_elems) : nullptr;

    dim3 blk(D4, NY);                    // 384 threads
    dim3 grd((BB * ML) / RPB);           // 2048 blocks
    lr_fused_kernel<<<grd, blk>>>((const float4*)x, dur, (float4*)out, mel_out);
}

// round 12
// speedup vs baseline: 1.2020x; 1.0918x over previous
#include <cuda_runtime.h>
#include <stdint.h>

// Problem constants (fixed by the reference)
#define BB 32
#define TT 256
#define DD 384
#define ML 2048
#define D4 (DD / 4)   // 96 float4 per row
#define RPT 8         // rows per thread
#define NY 4          // y-slices per block
#define RPB (RPT*NY)  // 32 rows per block

// Streaming (evict-first) 128-bit store: output is write-once; keeping it
// out of L2 preserves x/idx residency across graph replays (proven R9 vs R10).
__device__ __forceinline__ void stg_cs_128(float4* p, float4 v) {
    asm volatile("st.global.cs.v4.f32 [%0], {%1, %2, %3, %4};"
                 :: "l"(p), "f"(v.x), "f"(v.y), "f"(v.z), "f"(v.w)
                 : "memory");
}

// Non-coherent 128-bit load with L1 evict-last: x rows are re-read by many
// blocks within the launch; keep them resident in L1.
__device__ __forceinline__ float4 ldg_el_128(const float4* p) {
    float4 v;
    asm volatile("ld.global.nc.L1::evict_last.v4.f32 {%0, %1, %2, %3}, [%4];"
                 : "=f"(v.x), "=f"(v.y), "=f"(v.z), "=f"(v.w) : "l"(p));
    return v;
}

// Single fused kernel (R9 structure). Block = (96,4) = 384 threads; 32
// consecutive output rows of one batch per block. Prelude: shfl scan
// (3 barriers) + scatter of the block's 32-row idx window. Gather: 8
// independent evict-last loads per thread (MLP=8), 8 streaming stores.
__global__ void __launch_bounds__(384, 5)
lr_fused_kernel(const float4* __restrict__ x,
                const int* __restrict__ dur,
                float4* __restrict__ out,
                float* __restrict__ mel_out) {
    __shared__ int cs[TT];         // inclusive cumsum of durations
    __shared__ int wsum[TT / 32];  // per-warp totals (8)
    __shared__ int sidx[RPB];      // source-token idx for block rows (-1 = pad)

    const int tid  = threadIdx.y * blockDim.x + threadIdx.x;  // 0..383
    const int r0   = blockIdx.x * RPB;       // first output row of this block
    const int b    = r0 >> 11;               // batch = r0 / ML
    const int rloc = r0 & (ML - 1);          // row offset within batch

    // init idx window
    if (tid >= TT && tid < TT + RPB) sidx[tid - TT] = -1;

    int myd = 0;
    if (tid < TT) {
        const int lane = tid & 31;
        const int w    = tid >> 5;           // warp 0..7
        myd = __ldg(&dur[b * TT + tid]);

        // warp-level inclusive scan (5 shfl steps)
        int s = myd;
        #pragma unroll
        for (int off = 1; off < 32; off <<= 1) {
            int up = __shfl_up_sync(0xFFFFFFFFu, s, off);
            if (lane >= off) s += up;
        }
        cs[tid] = s;
        if (lane == 31) wsum[w] = s;
    }
    __syncthreads();

    if (tid < TT) {
        const int w = tid >> 5;
        int off = 0;
        #pragma unroll
        for (int i = 0; i < TT / 32 - 1; i++)
            if (i < w) off += wsum[i];
        const int incl = cs[tid] + off;      // inclusive prefix
        cs[tid] = incl;

        // mel_len (float32 tail — proven R4->R5); one block per batch writes
        if (tid == TT - 1 && rloc == 0 && mel_out != nullptr)
            mel_out[b] = (float)incl;
    }
    __syncthreads();

    // Scatter this block's 32-row window: token tid covers [start, end)
    if (tid < TT) {
        const int end   = cs[tid];
        const int start = end - myd;         // exclusive prefix
        int lo = start > rloc ? start : rloc;
        int hi = end < rloc + RPB ? end : rloc + RPB;
        for (int f = lo; f < hi; f++) sidx[f - rloc] = tid;
    }
    __syncthreads();

    // ---- gather: 8 rows per thread, MLP=8, evict-last loads ----
    const int j  = threadIdx.x;              // 0..95
    const int ry = threadIdx.y * RPT;        // this thread's first local row

    int idx[RPT];
    #pragma unroll
    for (int i = 0; i < RPT; i++) idx[i] = sidx[ry + i];

    float4 v[RPT];
    #pragma unroll
    for (int i = 0; i < RPT; i++) {
        v[i] = make_float4(0.f, 0.f, 0.f, 0.f);
        if (idx[i] >= 0) v[i] = ldg_el_128(&x[(b * TT + idx[i]) * D4 + j]);
    }

    float4* basep = (float4*)out + (long long)(r0 + ry) * D4 + j;
    #pragma unroll
    for (int i = 0; i < RPT; i++) stg_cs_128(basep + (long long)i * D4, v[i]);
}

extern "C" void kernel_launch(void* const* d_in, const int* in_sizes, int n_in,
                              void* d_out, int out_size) {
    const float* x   = (const float*)d_in[0];
    const int*   dur = (const int*)d_in[1];   // harness stores duration as int32
    // d_in[2] = max_len (scalar, constant 2048)

    float* out = (float*)d_out;
    const long long main_elems = (long long)BB * ML * DD;
    const long long extra = (long long)out_size - main_elems;
    float* mel_out = (extra > 0) ? (out + main_elems) : nullptr;

    dim3 blk(D4, NY);                    // 384 threads
    dim3 grd((BB * ML) / RPB);           // 2048 blocks
    lr_fused_kernel<<<grd, blk>>>((const float4*)x, dur, (float4*)out, mel_out);
}